// round 3
// baseline (speedup 1.0000x reference)
#include <cuda_runtime.h>

#define BSZ 2048
#define LSZ 200
#define DSZ 256

// Scratch (device globals — no allocation allowed). Kernels reference these
// directly; kernel_launch contains ONLY kernel launches (graph-capture safe).
__device__ float g_M[DSZ * DSZ];     // W_query @ W_key^T
__device__ float g_QK[BSZ * DSZ];    // q @ M
__device__ float g_CTX[BSZ * DSZ];   // softmax-weighted sum of k rows

// ---------------------------------------------------------------------------
// Kernel 0: g_M[256,256] = Wq[256,256] @ Wk[256,256]^T
// ---------------------------------------------------------------------------
__global__ void mm_abt_kernel(const float* __restrict__ A,
                              const float* __restrict__ B)
{
    __shared__ float As[16][64];
    __shared__ float Bs[16][64];
    const int tid = threadIdx.x;
    const int tx = tid & 15, ty = tid >> 4;
    const int row0 = blockIdx.y * 64, col0 = blockIdx.x * 64;

    float acc[4][4] = {};
    for (int k0 = 0; k0 < 256; k0 += 16) {
        #pragma unroll
        for (int r = 0; r < 4; r++) {
            int idx = tid + r * 256;            // 0..1023
            int ar = idx >> 4, ak = idx & 15;   // 64 x 16 tile
            As[ak][ar] = A[(row0 + ar) * 256 + k0 + ak];
            Bs[ak][ar] = B[(col0 + ar) * 256 + k0 + ak];   // B^T access
        }
        __syncthreads();
        #pragma unroll
        for (int kk = 0; kk < 16; kk++) {
            float av[4], bv[4];
            #pragma unroll
            for (int i = 0; i < 4; i++) av[i] = As[kk][ty * 4 + i];
            #pragma unroll
            for (int j = 0; j < 4; j++) bv[j] = Bs[kk][tx * 4 + j];
            #pragma unroll
            for (int i = 0; i < 4; i++)
                #pragma unroll
                for (int j = 0; j < 4; j++)
                    acc[i][j] += av[i] * bv[j];
        }
        __syncthreads();
    }
    #pragma unroll
    for (int i = 0; i < 4; i++)
        #pragma unroll
        for (int j = 0; j < 4; j++)
            g_M[(row0 + ty * 4 + i) * 256 + col0 + tx * 4 + j] = acc[i][j];
}

// ---------------------------------------------------------------------------
// C[2048,256] = A[2048,256] @ B[256,256]   (row-major). Grid (4, 32), 256 thr.
// Used for QK = q @ g_M (A=q, B=g_M, C=g_QK) and out = g_CTX @ Wv.
// A/B/C passed as pointers; scratch pointers resolve via device globals in
// wrapper kernels below.
// ---------------------------------------------------------------------------
__device__ __forceinline__ void sgemm256_body(const float* __restrict__ A,
                                              const float* __restrict__ B,
                                              float* __restrict__ C)
{
    __shared__ float As[16][64];
    __shared__ float Bs[16][64];
    const int tid = threadIdx.x;
    const int tx = tid & 15, ty = tid >> 4;
    const int row0 = blockIdx.y * 64, col0 = blockIdx.x * 64;

    float acc[4][4] = {};
    for (int k0 = 0; k0 < 256; k0 += 16) {
        #pragma unroll
        for (int r = 0; r < 4; r++) {
            int idx = tid + r * 256;
            int ar = idx >> 4, ak = idx & 15;          // A tile: 64 rows x 16 k
            As[ak][ar] = A[(row0 + ar) * 256 + k0 + ak];
            int bk = (tid >> 6) + r * 4;               // B tile: 16 k x 64 cols
            int bn = tid & 63;
            Bs[bk][bn] = B[(k0 + bk) * 256 + col0 + bn];
        }
        __syncthreads();
        #pragma unroll
        for (int kk = 0; kk < 16; kk++) {
            float av[4], bv[4];
            #pragma unroll
            for (int i = 0; i < 4; i++) av[i] = As[kk][ty * 4 + i];
            #pragma unroll
            for (int j = 0; j < 4; j++) bv[j] = Bs[kk][tx * 4 + j];
            #pragma unroll
            for (int i = 0; i < 4; i++)
                #pragma unroll
                for (int j = 0; j < 4; j++)
                    acc[i][j] += av[i] * bv[j];
        }
        __syncthreads();
    }
    #pragma unroll
    for (int i = 0; i < 4; i++)
        #pragma unroll
        for (int j = 0; j < 4; j++)
            C[(row0 + ty * 4 + i) * 256 + col0 + tx * 4 + j] = acc[i][j];
}

// QK = q @ g_M
__global__ void qk_gemm_kernel(const float* __restrict__ q)
{
    sgemm256_body(q, g_M, g_QK);
}

// out = g_CTX @ Wv
__global__ void out_gemm_kernel(const float* __restrict__ Wv,
                                float* __restrict__ out)
{
    sgemm256_body(g_CTX, Wv, out);
}

// ---------------------------------------------------------------------------
// Main kernel: one CTA per batch. Streams k[b] (200x256 fp32, 204.8 KB) once.
//   score[l] = k[b,l] . QK[b] + bias*256
//   logit[l] = mask ? sigmoid(score)/16 : PAD/16
//   w = softmax(logit);  CTX[b] = sum_l w[l] * k[b,l]
// Fixed-max softmax: valid logits in (0, 1/16], exp(logit - 1/16) is safe;
// masked logits = PAD/16 ~ -2.7e8 underflow to exactly 0.
// len==0 -> all PAD -> softmax over equal values -> uniform (p=1 for all l).
// ---------------------------------------------------------------------------
__global__ void attn_kernel(const float* __restrict__ K,
                            const int* __restrict__ keys_length,
                            const float* __restrict__ bias)
{
    __shared__ float sZ[8];
    __shared__ float sctx[8][DSZ];

    const int b = blockIdx.x;
    const int tid = threadIdx.x;
    const int w = tid >> 5;
    const int lane = tid & 31;

    const float* kb = K + (size_t)b * LSZ * DSZ;

    // per-lane slice of QK[b]: dims [lane*8, lane*8+8)
    const float4* qkp = (const float4*)(g_QK + (size_t)b * DSZ + lane * 8);
    const float4 q0 = qkp[0];
    const float4 q1 = qkp[1];

    const int len = keys_length[b];
    const float b256 = bias[0] * 256.0f;

    float Z = 0.0f;
    float c0 = 0.f, c1 = 0.f, c2 = 0.f, c3 = 0.f;
    float c4 = 0.f, c5 = 0.f, c6 = 0.f, c7 = 0.f;

    #pragma unroll 5
    for (int i = 0; i < LSZ / 8; i++) {
        const int l = i * 8 + w;
        const float4* kr = (const float4*)(kb + l * DSZ + lane * 8);
        const float4 a0 = __ldg(kr);
        const float4 a1 = __ldg(kr + 1);

        float dot = a0.x * q0.x + a0.y * q0.y + a0.z * q0.z + a0.w * q0.w
                  + a1.x * q1.x + a1.y * q1.y + a1.z * q1.z + a1.w * q1.w;
        #pragma unroll
        for (int off = 16; off > 0; off >>= 1)
            dot += __shfl_xor_sync(0xffffffffu, dot, off);

        float p;
        if (len == 0) {
            p = 1.0f;                       // all masked -> uniform softmax
        } else if (l < len) {
            const float score = dot + b256;
            const float sig = 1.0f / (1.0f + __expf(-score));
            p = __expf(sig * 0.0625f - 0.0625f);   // exp(logit - 1/16)
        } else {
            p = 0.0f;                       // masked: exp underflows to 0
        }

        Z += p;
        c0 += p * a0.x; c1 += p * a0.y; c2 += p * a0.z; c3 += p * a0.w;
        c4 += p * a1.x; c5 += p * a1.y; c6 += p * a1.z; c7 += p * a1.w;
    }

    if (lane == 0) sZ[w] = Z;   // Z identical across lanes (butterfly reduce)
    const int d = lane * 8;
    sctx[w][d + 0] = c0; sctx[w][d + 1] = c1; sctx[w][d + 2] = c2; sctx[w][d + 3] = c3;
    sctx[w][d + 4] = c4; sctx[w][d + 5] = c5; sctx[w][d + 6] = c6; sctx[w][d + 7] = c7;
    __syncthreads();

    float zt = 0.0f;
    #pragma unroll
    for (int ww = 0; ww < 8; ww++) zt += sZ[ww];
    float c = 0.0f;
    #pragma unroll
    for (int ww = 0; ww < 8; ww++) c += sctx[ww][tid];

    g_CTX[(size_t)b * DSZ + tid] = c / zt;
}

// ---------------------------------------------------------------------------
extern "C" void kernel_launch(void* const* d_in, const int* in_sizes, int n_in,
                              void* d_out, int out_size)
{
    const float* q      = (const float*)d_in[0];   // [2048, 1, 256]
    const float* k      = (const float*)d_in[1];   // [2048, 200, 256]
    // d_in[2] = v: unused (reference derives both k and v paths from input k)
    const int*   klen   = (const int*)d_in[3];     // [2048, 1]
    const float* Wq     = (const float*)d_in[4];   // [256, 256]
    const float* Wk     = (const float*)d_in[5];   // [256, 256]
    const float* Wv     = (const float*)d_in[6];   // [256, 256]
    const float* bias   = (const float*)d_in[7];   // [1]
    float* out = (float*)d_out;                    // [2048, 1, 256]

    // 1) M = Wq @ Wk^T
    mm_abt_kernel<<<dim3(4, 4), 256>>>(Wq, Wk);
    // 2) QK = q @ M   [2048,256]
    qk_gemm_kernel<<<dim3(4, 32), 256>>>(q);
    // 3) attention in k-space -> CTX [2048,256]
    attn_kernel<<<BSZ, 256>>>(k, klen, bias);
    // 4) out = CTX @ Wv
    out_gemm_kernel<<<dim3(4, 32), 256>>>(Wv, out);
}